// round 8
// baseline (speedup 1.0000x reference)
#include <cuda_runtime.h>
#include <math.h>
#include <stddef.h>
#include <stdint.h>

// Problem constants
#define B_  2
#define S_  2048
#define D_  1024
#define H_  16
#define FK_ 32
#define DK_ 64
#define BH_ (B_*H_)

#define CAP_HALF 128          // per half-row candidate cap (gmem segment)

// ---------------- scratch (__device__ globals; no allocation allowed) ----------------
__device__ float g_M[H_*DK_*DK_];         // collapsed 64x64 (for exact rescore path via Qp)
__device__ float g_L[H_*DK_*FK_];         // L[h] = Wa@Wb@Wa2 (64x32), fp64-collapsed
__device__ float g_Qp[B_*S_*D_];          // [B,S,D] (h*64+d)
__device__ float g_vp[B_*S_*D_];          // v@Wv+bv
__device__ float g_concat[B_*S_*D_];      // attention output pre-Wo
__device__ float g_X[BH_*S_*FK_];         // X[bh][s][32] = q.L
__device__ float g_Y[BH_*S_*FK_];         // Y[bh][t][32] = q.R^T
// candidate lists per (bh,s) row: two half-segments of CAP_HALF each
__device__ int g_ct[(size_t)BH_*S_*2*CAP_HALF];
__device__ int g_cn[BH_*S_*2];            // TRUE counts (may exceed CAP_HALF -> flagged)

// ---------------- 1) collapse the low-rank chain per head, in fp64 ----------------
// Also emits L[h] = Wa@Wb@Wa2 (the 64x32 left factor of M = L@R, R = Wb2).
__global__ void compute_M_kernel(const float* __restrict__ W_A,
                                 const float* __restrict__ W_A2) {
    int h = blockIdx.x;
    __shared__ double T1[64*64];
    __shared__ double T2[64*32];
    const float* WAh  = W_A  + h*2048;
    const float* WA2h = W_A2 + h*2048;

    for (int idx = threadIdx.x; idx < 4096; idx += blockDim.x) {
        int c = idx >> 6, d = idx & 63;
        double acc = 0.0;
        #pragma unroll 8
        for (int j = 0; j < 32; j++)
            acc += (double)WAh[c*32 + j] * (double)WAh[j*64 + d];
        T1[idx] = acc;
    }
    __syncthreads();
    for (int idx = threadIdx.x; idx < 2048; idx += blockDim.x) {
        int c = idx >> 5, j = idx & 31;
        double acc = 0.0;
        #pragma unroll 8
        for (int d = 0; d < 64; d++)
            acc += T1[c*64 + d] * (double)WA2h[d*32 + j];
        T2[idx] = acc;
        g_L[h*2048 + idx] = (float)acc;
    }
    __syncthreads();
    for (int idx = threadIdx.x; idx < 4096; idx += blockDim.x) {
        int c = idx >> 6, d = idx & 63;
        double acc = 0.0;
        #pragma unroll 8
        for (int j = 0; j < 32; j++)
            acc += T2[c*32 + j] * (double)WA2h[j*64 + d];
        g_M[h*4096 + idx] = (float)acc;
    }
}

// ---------------- 2) Qp = q @ M[h] per head (for exact rescoring) ----------------
__global__ void qp_kernel(const float* __restrict__ q) {
    int token = blockIdx.x;
    __shared__ float qs[D_];
    const float* qrow = q + (size_t)token * D_;
    for (int i = threadIdx.x; i < D_; i += 256) qs[i] = qrow[i];
    __syncthreads();
    int d  = threadIdx.x & 63;
    int h0 = threadIdx.x >> 6;
    float* out = g_Qp + (size_t)token * D_;
    #pragma unroll
    for (int hh = 0; hh < 4; hh++) {
        int h = h0 * 4 + hh;
        const float* Mh = g_M + h*4096;
        const float* qh = qs + h*64;
        float acc = 0.f;
        #pragma unroll 8
        for (int c = 0; c < 64; c++) acc = fmaf(qh[c], Mh[c*64 + d], acc);
        out[h*64 + d] = acc;
    }
}

// ---------------- 2b) X = q.L, Y = q.R^T per head (rank-32 factors) ----------------
__global__ __launch_bounds__(512)
void xy_kernel(const float* __restrict__ q, const float* __restrict__ W_A2) {
    int token = blockIdx.x;                  // b*2048+s
    int b = token >> 11, s = token & 2047;
    __shared__ float qs[D_];
    const float* qrow = q + (size_t)token * D_;
    for (int i = threadIdx.x; i < D_; i += 512) qs[i] = qrow[i];
    __syncthreads();
    int j = threadIdx.x & 31;
    int h = threadIdx.x >> 5;               // 0..15
    const float* qh = qs + h*64;
    // X[j] = sum_c q[c] * L[h][c][j]
    const float* Lh = g_L + h*2048 + j;
    float x = 0.f;
    #pragma unroll 8
    for (int c = 0; c < 64; c++) x = fmaf(qh[c], Lh[c*32], x);
    // Y[j] = sum_d q[d] * Wb2[h][j][d],  Wb2[h][j][d] = W_A2[h*2048 + j*64 + d]
    const float* Rh = W_A2 + h*2048 + j*64;
    float y = 0.f;
    #pragma unroll 8
    for (int d = 0; d < 64; d++) y = fmaf(qh[d], Rh[d], y);
    size_t o = (((size_t)(b*16 + h))*2048 + s)*32 + j;
    g_X[o] = x;
    g_Y[o] = y;
}

// ---------------- 3) scalar SGEMM (R1, at SIMT fp32 ceiling) ----------------
__global__ __launch_bounds__(256)
void sgemm_nn_bias(int M, int N, int K,
                   const float* __restrict__ A,
                   const float* __restrict__ Bm,
                   const float* __restrict__ bias,
                   float* __restrict__ C) {
    __shared__ float As[16][128];
    __shared__ float Bs[16][128];
    int bm = blockIdx.y * 128;
    int bn = blockIdx.x * 128;
    int tid = threadIdx.x;
    int tx = tid & 15, ty = tid >> 4;

    float acc[8][8];
    #pragma unroll
    for (int i = 0; i < 8; i++)
        #pragma unroll
        for (int j = 0; j < 8; j++) acc[i][j] = 0.f;

    int arow = tid >> 1;
    int acol = (tid & 1) * 8;
    int brow = tid >> 4;
    int bcol = (tid & 15) * 8;

    for (int k0 = 0; k0 < K; k0 += 16) {
        const float* Ap = A + (size_t)(bm + arow) * K + k0 + acol;
        float4 a0 = *(const float4*)Ap;
        float4 a1 = *(const float4*)(Ap + 4);
        As[acol+0][arow] = a0.x; As[acol+1][arow] = a0.y;
        As[acol+2][arow] = a0.z; As[acol+3][arow] = a0.w;
        As[acol+4][arow] = a1.x; As[acol+5][arow] = a1.y;
        As[acol+6][arow] = a1.z; As[acol+7][arow] = a1.w;

        const float* Bp = Bm + (size_t)(k0 + brow) * N + bn + bcol;
        *(float4*)&Bs[brow][bcol]     = *(const float4*)Bp;
        *(float4*)&Bs[brow][bcol + 4] = *(const float4*)(Bp + 4);
        __syncthreads();

        #pragma unroll
        for (int kk = 0; kk < 16; kk++) {
            float a[8], b[8];
            *(float4*)(a)     = *(float4*)&As[kk][ty*8];
            *(float4*)(a + 4) = *(float4*)&As[kk][ty*8 + 4];
            *(float4*)(b)     = *(float4*)&Bs[kk][tx*8];
            *(float4*)(b + 4) = *(float4*)&Bs[kk][tx*8 + 4];
            #pragma unroll
            for (int i = 0; i < 8; i++)
                #pragma unroll
                for (int j = 0; j < 8; j++)
                    acc[i][j] = fmaf(a[i], b[j], acc[i][j]);
        }
        __syncthreads();
    }

    #pragma unroll
    for (int i = 0; i < 8; i++) {
        int row = bm + ty*8 + i;
        float* Cp = C + (size_t)row * N + bn + tx*8;
        float o[8];
        #pragma unroll
        for (int j = 0; j < 8; j++)
            o[j] = acc[i][j] + bias[bn + tx*8 + j];
        *(float4*)(Cp)     = *(float4*)(o);
        *(float4*)(Cp + 4) = *(float4*)(o + 4);
    }
}

// ---------------- 4) fp32 K=32 scores (X.Y^T) + streaming candidate capture ----
// Grid (16 s-tiles, 32 bh), 256 threads. Per t-tile: K=32 SIMT GEMM (fp32, so
// approx error ~0.1 on 1e5-scale logits) -> smem fp32 tile -> scan 2 thr/row.
// Margin 110 + 1e-4*rmax covers the 104 softmax-support window plus all fp32
// path differences. Overflowing rows (tiny-scale, wide support) are flagged via
// true count and handled densely in the exact pass.
#define SM_A  0
#define SM_B  16384
#define SM_SC 32768
#define SMEM_SCORES 98304

__global__ __launch_bounds__(256)
void scores_fp32_kernel() {
    extern __shared__ __align__(128) char sm[];
    float* As = (float*)(sm + SM_A);      // [32][128]  As[k][row]
    float* Bs = (float*)(sm + SM_B);      // [32][128]  Bs[k][col]
    float* SC = (float*)(sm + SM_SC);     // [128][128]

    int tid = threadIdx.x;
    int stile = blockIdx.x, bh = blockIdx.y;
    int s0 = stile * 128;
    int tx = tid & 15, ty = tid >> 4;
    int row = tid >> 1, half = tid & 1;

    const float* X = g_X + ((size_t)bh*2048 + s0)*32;
    const float* Y = g_Y + (size_t)bh*2048*32;

    // ---- stage A (transposed) once ----
    {
        const float4* xr = (const float4*)(X + row*32 + half*16);
        float4 v0 = xr[0], v1 = xr[1], v2 = xr[2], v3 = xr[3];
        int k0 = half*16;
        As[(k0+ 0)*128+row]=v0.x; As[(k0+ 1)*128+row]=v0.y; As[(k0+ 2)*128+row]=v0.z; As[(k0+ 3)*128+row]=v0.w;
        As[(k0+ 4)*128+row]=v1.x; As[(k0+ 5)*128+row]=v1.y; As[(k0+ 6)*128+row]=v1.z; As[(k0+ 7)*128+row]=v1.w;
        As[(k0+ 8)*128+row]=v2.x; As[(k0+ 9)*128+row]=v2.y; As[(k0+10)*128+row]=v2.z; As[(k0+11)*128+row]=v2.w;
        As[(k0+12)*128+row]=v3.x; As[(k0+13)*128+row]=v3.y; As[(k0+14)*128+row]=v3.z; As[(k0+15)*128+row]=v3.w;
    }

    // ---- per-thread scan state: row tid>>1, col half tid&1 ----
    int rowg = bh*2048 + s0 + row;
    int* seg = g_ct + ((size_t)rowg * 2 + half) * CAP_HALF;
    float rmax = -3.0e38f;
    int cnt = 0;

    for (int tt = 0; tt < 16; tt++) {
        int t0 = tt * 128;
        // stage B tile (transposed)
        {
            const float4* yr = (const float4*)(Y + (size_t)(t0 + row)*32 + half*16);
            float4 v0 = yr[0], v1 = yr[1], v2 = yr[2], v3 = yr[3];
            int k0 = half*16;
            Bs[(k0+ 0)*128+row]=v0.x; Bs[(k0+ 1)*128+row]=v0.y; Bs[(k0+ 2)*128+row]=v0.z; Bs[(k0+ 3)*128+row]=v0.w;
            Bs[(k0+ 4)*128+row]=v1.x; Bs[(k0+ 5)*128+row]=v1.y; Bs[(k0+ 6)*128+row]=v1.z; Bs[(k0+ 7)*128+row]=v1.w;
            Bs[(k0+ 8)*128+row]=v2.x; Bs[(k0+ 9)*128+row]=v2.y; Bs[(k0+10)*128+row]=v2.z; Bs[(k0+11)*128+row]=v2.w;
            Bs[(k0+12)*128+row]=v3.x; Bs[(k0+13)*128+row]=v3.y; Bs[(k0+14)*128+row]=v3.z; Bs[(k0+15)*128+row]=v3.w;
        }
        __syncthreads();

        float acc[8][8];
        #pragma unroll
        for (int i = 0; i < 8; i++)
            #pragma unroll
            for (int j = 0; j < 8; j++) acc[i][j] = 0.f;

        #pragma unroll
        for (int kk = 0; kk < 32; kk++) {
            float a[8], b[8];
            *(float4*)(a)     = *(float4*)&As[kk*128 + ty*8];
            *(float4*)(a + 4) = *(float4*)&As[kk*128 + ty*8 + 4];
            *(float4*)(b)     = *(float4*)&Bs[kk*128 + tx*8];
            *(float4*)(b + 4) = *(float4*)&Bs[kk*128 + tx*8 + 4];
            #pragma unroll
            for (int i = 0; i < 8; i++)
                #pragma unroll
                for (int j = 0; j < 8; j++)
                    acc[i][j] = fmaf(a[i], b[j], acc[i][j]);
        }

        // spill acc -> SC
        #pragma unroll
        for (int i = 0; i < 8; i++) {
            *(float4*)&SC[(ty*8+i)*128 + tx*8]     = *(float4*)&acc[i][0];
            *(float4*)&SC[(ty*8+i)*128 + tx*8 + 4] = *(float4*)&acc[i][4];
        }
        __syncthreads();

        // scan my half row; adaptive threshold; stream captures to private seg
        const float* rp = SC + row*128 + half*64;
        int tglob0 = t0 + half*64;
        #pragma unroll 4
        for (int j4 = 0; j4 < 16; j4++) {
            float4 x4 = *(const float4*)(rp + j4*4);
            float xs[4] = {x4.x, x4.y, x4.z, x4.w};
            #pragma unroll
            for (int u = 0; u < 4; u++) {
                float x = xs[u];
                float thr = rmax - 110.0f - 1e-4f * fmaxf(rmax, 0.0f);
                if (x > thr) {
                    if (cnt < CAP_HALF) seg[cnt] = tglob0 + j4*4 + u;
                    cnt++;
                }
                if (x > rmax) rmax = x;
            }
        }
        __syncthreads();   // scans done before next SC overwrite / B restage
    }

    g_cn[rowg*2 + half] = cnt;   // true count; > CAP_HALF means "flagged"
}

// ---------------- 5) exact softmax + PV: sparse path, dense fallback ----------
__global__ __launch_bounds__(64)
void exact_softmax_pv_kernel(const float* __restrict__ q) {
    int row = blockIdx.x;                 // bh*2048 + s
    int bh = row >> 11, s = row & 2047;
    int b = bh >> 4, h = bh & 15;

    __shared__ float qp_s[64];
    __shared__ int   ts[2*CAP_HALF];
    __shared__ float ex[2*CAP_HALF];
    __shared__ float sc2[S_];             // dense fallback scores/weights
    __shared__ float red[64];
    __shared__ float s_denom;

    int tid = threadIdx.x;
    int n0 = g_cn[row*2], n1 = g_cn[row*2 + 1];

    qp_s[tid] = g_Qp[((size_t)(b*2048 + s))*D_ + h*64 + tid];
    __syncthreads();

    const float* qbase  = q    + ((size_t)b*2048)*D_ + h*64;
    const float* vpbase = g_vp + ((size_t)b*2048)*D_ + h*64;

    if (n0 > CAP_HALF || n1 > CAP_HALF) {
        // ---------- DENSE fallback (rare: tiny-scale rows, wide support) ----------
        for (int t = tid; t < S_; t += 64) {
            const float* qr = qbase + (size_t)t * D_;
            float acc = 0.f;
            #pragma unroll 16
            for (int kk = 0; kk < 64; kk++) acc = fmaf(qp_s[kk], qr[kk], acc);
            sc2[t] = acc;
        }
        __syncthreads();
        float pm = -3.0e38f;
        for (int t = tid; t < S_; t += 64) pm = fmaxf(pm, sc2[t]);
        red[tid] = pm; __syncthreads();
        if (tid == 0) {
            float m = red[0];
            for (int i = 1; i < 64; i++) m = fmaxf(m, red[i]);
            red[0] = m;
        }
        __syncthreads();
        float m = red[0];
        __syncthreads();
        float ps = 0.f;
        for (int t = tid; t < S_; t += 64) {
            float w = expf(sc2[t] - m);
            sc2[t] = w;
            ps += w;
        }
        red[tid] = ps; __syncthreads();
        if (tid == 0) {
            float den = 0.f;
            for (int i = 0; i < 64; i++) den += red[i];
            s_denom = den;
        }
        __syncthreads();
        float o = 0.f;
        for (int t = 0; t < S_; t++) {
            float w = sc2[t];
            if (w != 0.0f) o = fmaf(w, vpbase[(size_t)t * D_ + tid], o);
        }
        g_concat[((size_t)(b*2048 + s))*D_ + h*64 + tid] = o / s_denom;
        return;
    }

    // ---------- SPARSE path ----------
    int n = n0 + n1;
    const int* seg0 = g_ct + (size_t)row * 2 * CAP_HALF;
    for (int i = tid; i < n0; i += 64) ts[i]      = seg0[i];
    for (int i = tid; i < n1; i += 64) ts[n0 + i] = seg0[CAP_HALF + i];
    __syncthreads();

    for (int i = tid; i < n; i += 64) {
        const float* qr = qbase + (size_t)ts[i] * D_;
        float acc = 0.f;
        #pragma unroll 16
        for (int kk = 0; kk < 64; kk++) acc = fmaf(qp_s[kk], qr[kk], acc);
        ex[i] = acc;
    }
    __syncthreads();

    if (tid == 0) {
        float emax = ex[0];
        for (int i = 1; i < n; i++) emax = fmaxf(emax, ex[i]);
        float den = 0.f;
        for (int i = 0; i < n; i++) { float w = expf(ex[i] - emax); ex[i] = w; den += w; }
        s_denom = den;
    }
    __syncthreads();

    float o = 0.f;
    for (int i = 0; i < n; i++) {
        float w = ex[i];
        if (w != 0.0f)
            o = fmaf(w, vpbase[(size_t)ts[i] * D_ + tid], o);
    }
    g_concat[((size_t)(b*2048 + s))*D_ + h*64 + tid] = o / s_denom;
}

// ---------------- launcher ----------------
extern "C" void kernel_launch(void* const* d_in, const int* in_sizes, int n_in,
                              void* d_out, int out_size) {
    const float* q    = (const float*)d_in[0];
    // d_in[1] = k (unused in reference forward)
    const float* v    = (const float*)d_in[2];
    const float* Wv   = (const float*)d_in[3];
    const float* bv   = (const float*)d_in[4];
    const float* W_A  = (const float*)d_in[5];
    const float* W_A2 = (const float*)d_in[6];
    const float* Wo   = (const float*)d_in[7];
    const float* bo   = (const float*)d_in[8];
    float* out = (float*)d_out;

    float* vp;     cudaGetSymbolAddress((void**)&vp,     g_vp);
    float* concat; cudaGetSymbolAddress((void**)&concat, g_concat);

    cudaFuncSetAttribute(scores_fp32_kernel,
                         cudaFuncAttributeMaxDynamicSharedMemorySize, SMEM_SCORES);

    compute_M_kernel<<<H_, 256>>>(W_A, W_A2);
    qp_kernel<<<B_*S_, 256>>>(q);
    xy_kernel<<<B_*S_, 512>>>(q, W_A2);
    sgemm_nn_bias<<<dim3(D_/128, (B_*S_)/128), 256>>>(B_*S_, D_, D_, v, Wv, bv, vp);
    scores_fp32_kernel<<<dim3(S_/128, BH_), 256, SMEM_SCORES>>>();
    exact_softmax_pv_kernel<<<BH_*S_, 64>>>(q);
    sgemm_nn_bias<<<dim3(D_/128, (B_*S_)/128), 256>>>(B_*S_, D_, D_, concat, Wo, bo, out);
}

// round 9
// speedup vs baseline: 1.0684x; 1.0684x over previous
#include <cuda_runtime.h>
#include <math.h>
#include <stddef.h>
#include <stdint.h>

// Problem constants
#define B_  2
#define S_  2048
#define D_  1024
#define H_  16
#define FK_ 32
#define DK_ 64
#define BH_ (B_*H_)

// ---------------- scratch (__device__ globals; no allocation allowed) ----------------
__device__ float g_L[H_*DK_*FK_];         // L[h] = Wa@Wb@Wa2 (64x32), fp64-collapsed
__device__ float g_vp[B_*S_*D_];          // v@Wv+bv
__device__ float g_concat[B_*S_*D_];      // attention output pre-Wo
__device__ float g_X[BH_*S_*FK_];         // X[bh][s][32] = q.L
__device__ float g_Y[BH_*S_*FK_];         // Y[bh][t][32] = q.R^T

// ---------------- 1) collapse Wa@Wb@Wa2 per head, in fp64 ----------------
__global__ void compute_L_kernel(const float* __restrict__ W_A,
                                 const float* __restrict__ W_A2) {
    int h = blockIdx.x;
    __shared__ double T1[64*64];
    const float* WAh  = W_A  + h*2048;
    const float* WA2h = W_A2 + h*2048;

    for (int idx = threadIdx.x; idx < 4096; idx += blockDim.x) {
        int c = idx >> 6, d = idx & 63;
        double acc = 0.0;
        #pragma unroll 8
        for (int j = 0; j < 32; j++)
            acc += (double)WAh[c*32 + j] * (double)WAh[j*64 + d];
        T1[idx] = acc;
    }
    __syncthreads();
    for (int idx = threadIdx.x; idx < 2048; idx += blockDim.x) {
        int c = idx >> 5, j = idx & 31;
        double acc = 0.0;
        #pragma unroll 8
        for (int d = 0; d < 64; d++)
            acc += T1[c*64 + d] * (double)WA2h[d*32 + j];
        g_L[h*2048 + idx] = (float)acc;
    }
}

// ---------------- 2) X = q.L, Y = q.R^T per head (rank-32 factors) ----------------
__global__ __launch_bounds__(512)
void xy_kernel(const float* __restrict__ q, const float* __restrict__ W_A2) {
    int token = blockIdx.x;                  // b*2048+s
    int b = token >> 11, s = token & 2047;
    __shared__ float qs[D_];
    const float* qrow = q + (size_t)token * D_;
    for (int i = threadIdx.x; i < D_; i += 512) qs[i] = qrow[i];
    __syncthreads();
    int j = threadIdx.x & 31;
    int h = threadIdx.x >> 5;               // 0..15
    const float* qh = qs + h*64;
    const float* Lh = g_L + h*2048 + j;
    float x = 0.f;
    #pragma unroll 8
    for (int c = 0; c < 64; c++) x = fmaf(qh[c], Lh[c*32], x);
    const float* Rh = W_A2 + h*2048 + j*64;   // Wb2[h][j][d]
    float y = 0.f;
    #pragma unroll 8
    for (int d = 0; d < 64; d++) y = fmaf(qh[d], Rh[d], y);
    size_t o = (((size_t)(b*16 + h))*2048 + s)*32 + j;
    g_X[o] = x;
    g_Y[o] = y;
}

// ---------------- 3) scalar SGEMM (R1, at SIMT fp32 ceiling) ----------------
__global__ __launch_bounds__(256)
void sgemm_nn_bias(int M, int N, int K,
                   const float* __restrict__ A,
                   const float* __restrict__ Bm,
                   const float* __restrict__ bias,
                   float* __restrict__ C) {
    __shared__ float As[16][128];
    __shared__ float Bs[16][128];
    int bm = blockIdx.y * 128;
    int bn = blockIdx.x * 128;
    int tid = threadIdx.x;
    int tx = tid & 15, ty = tid >> 4;

    float acc[8][8];
    #pragma unroll
    for (int i = 0; i < 8; i++)
        #pragma unroll
        for (int j = 0; j < 8; j++) acc[i][j] = 0.f;

    int arow = tid >> 1;
    int acol = (tid & 1) * 8;
    int brow = tid >> 4;
    int bcol = (tid & 15) * 8;

    for (int k0 = 0; k0 < K; k0 += 16) {
        const float* Ap = A + (size_t)(bm + arow) * K + k0 + acol;
        float4 a0 = *(const float4*)Ap;
        float4 a1 = *(const float4*)(Ap + 4);
        As[acol+0][arow] = a0.x; As[acol+1][arow] = a0.y;
        As[acol+2][arow] = a0.z; As[acol+3][arow] = a0.w;
        As[acol+4][arow] = a1.x; As[acol+5][arow] = a1.y;
        As[acol+6][arow] = a1.z; As[acol+7][arow] = a1.w;

        const float* Bp = Bm + (size_t)(k0 + brow) * N + bn + bcol;
        *(float4*)&Bs[brow][bcol]     = *(const float4*)Bp;
        *(float4*)&Bs[brow][bcol + 4] = *(const float4*)(Bp + 4);
        __syncthreads();

        #pragma unroll
        for (int kk = 0; kk < 16; kk++) {
            float a[8], b[8];
            *(float4*)(a)     = *(float4*)&As[kk][ty*8];
            *(float4*)(a + 4) = *(float4*)&As[kk][ty*8 + 4];
            *(float4*)(b)     = *(float4*)&Bs[kk][tx*8];
            *(float4*)(b + 4) = *(float4*)&Bs[kk][tx*8 + 4];
            #pragma unroll
            for (int i = 0; i < 8; i++)
                #pragma unroll
                for (int j = 0; j < 8; j++)
                    acc[i][j] = fmaf(a[i], b[j], acc[i][j]);
        }
        __syncthreads();
    }

    #pragma unroll
    for (int i = 0; i < 8; i++) {
        int row = bm + ty*8 + i;
        float* Cp = C + (size_t)row * N + bn + tx*8;
        float o[8];
        #pragma unroll
        for (int j = 0; j < 8; j++)
            o[j] = acc[i][j] + bias[bn + tx*8 + j];
        *(float4*)(Cp)     = *(float4*)(o);
        *(float4*)(Cp + 4) = *(float4*)(o + 4);
    }
}

// ---------------- 4) FUSED: scores (X.Y^T, fp32) + online softmax + sparse PV ----
// Grid (16 s-tiles, 32 bh), 256 threads. Per t-tile: K=32 GEMM -> PADDED smem
// spill (stride 132 floats: scan LDS is ~2-way, not 32-way) -> both threads of
// each row scan the full 128-col row, maintaining online-softmax state
// (m, den, o[32 dims]) in registers. Entries with exp(x-m)==0 (x < m-95) are
// skipped -- identical fp32 result to dense softmax+PV. No second pass needed.
#define SCS 132
#define SM_A  0
#define SM_B  16384
#define SM_SC 32768
#define SMEM_FUSED (32768 + 128*SCS*4)   // 100352 bytes

__global__ __launch_bounds__(256)
void fused_attn_kernel() {
    extern __shared__ __align__(128) char sm[];
    float* As = (float*)(sm + SM_A);      // [32][128]  As[k][row]
    float* Bs = (float*)(sm + SM_B);      // [32][128]  Bs[k][col]
    float* SC = (float*)(sm + SM_SC);     // [128][SCS]

    int tid = threadIdx.x;
    int stile = blockIdx.x, bh = blockIdx.y;
    int b = bh >> 4, h = bh & 15;
    int s0 = stile * 128;
    int tx = tid & 15, ty = tid >> 4;
    int row = tid >> 1, half = tid & 1;

    const float* X = g_X + ((size_t)bh*2048 + s0)*32;
    const float* Y = g_Y + (size_t)bh*2048*32;
    const float* vbase = g_vp + (size_t)b*2048*D_ + h*64 + half*32;

    // ---- stage A (transposed) once ----
    {
        const float4* xr = (const float4*)(X + row*32 + half*16);
        float4 v0 = xr[0], v1 = xr[1], v2 = xr[2], v3 = xr[3];
        int k0 = half*16;
        As[(k0+ 0)*128+row]=v0.x; As[(k0+ 1)*128+row]=v0.y; As[(k0+ 2)*128+row]=v0.z; As[(k0+ 3)*128+row]=v0.w;
        As[(k0+ 4)*128+row]=v1.x; As[(k0+ 5)*128+row]=v1.y; As[(k0+ 6)*128+row]=v1.z; As[(k0+ 7)*128+row]=v1.w;
        As[(k0+ 8)*128+row]=v2.x; As[(k0+ 9)*128+row]=v2.y; As[(k0+10)*128+row]=v2.z; As[(k0+11)*128+row]=v2.w;
        As[(k0+12)*128+row]=v3.x; As[(k0+13)*128+row]=v3.y; As[(k0+14)*128+row]=v3.z; As[(k0+15)*128+row]=v3.w;
    }

    // ---- online softmax / PV state (per thread; both halves track full row) ----
    float m   = __int_as_float(0xff800000);   // -inf
    float den = 0.f;
    float4 o4[8];
    #pragma unroll
    for (int jj = 0; jj < 8; jj++) o4[jj] = make_float4(0.f, 0.f, 0.f, 0.f);

    for (int tt = 0; tt < 16; tt++) {
        int t0 = tt * 128;
        // stage B tile (transposed)
        {
            const float4* yr = (const float4*)(Y + (size_t)(t0 + row)*32 + half*16);
            float4 v0 = yr[0], v1 = yr[1], v2 = yr[2], v3 = yr[3];
            int k0 = half*16;
            Bs[(k0+ 0)*128+row]=v0.x; Bs[(k0+ 1)*128+row]=v0.y; Bs[(k0+ 2)*128+row]=v0.z; Bs[(k0+ 3)*128+row]=v0.w;
            Bs[(k0+ 4)*128+row]=v1.x; Bs[(k0+ 5)*128+row]=v1.y; Bs[(k0+ 6)*128+row]=v1.z; Bs[(k0+ 7)*128+row]=v1.w;
            Bs[(k0+ 8)*128+row]=v2.x; Bs[(k0+ 9)*128+row]=v2.y; Bs[(k0+10)*128+row]=v2.z; Bs[(k0+11)*128+row]=v2.w;
            Bs[(k0+12)*128+row]=v3.x; Bs[(k0+13)*128+row]=v3.y; Bs[(k0+14)*128+row]=v3.z; Bs[(k0+15)*128+row]=v3.w;
        }
        __syncthreads();

        float acc[8][8];
        #pragma unroll
        for (int i = 0; i < 8; i++)
            #pragma unroll
            for (int j = 0; j < 8; j++) acc[i][j] = 0.f;

        #pragma unroll
        for (int kk = 0; kk < 32; kk++) {
            float a[8], bb[8];
            *(float4*)(a)      = *(float4*)&As[kk*128 + ty*8];
            *(float4*)(a + 4)  = *(float4*)&As[kk*128 + ty*8 + 4];
            *(float4*)(bb)     = *(float4*)&Bs[kk*128 + tx*8];
            *(float4*)(bb + 4) = *(float4*)&Bs[kk*128 + tx*8 + 4];
            #pragma unroll
            for (int i = 0; i < 8; i++)
                #pragma unroll
                for (int j = 0; j < 8; j++)
                    acc[i][j] = fmaf(a[i], bb[j], acc[i][j]);
        }

        // spill acc -> SC (padded stride)
        #pragma unroll
        for (int i = 0; i < 8; i++) {
            *(float4*)&SC[(ty*8+i)*SCS + tx*8]     = *(float4*)&acc[i][0];
            *(float4*)&SC[(ty*8+i)*SCS + tx*8 + 4] = *(float4*)&acc[i][4];
        }
        __syncthreads();

        // scan full row (both halves; broadcast LDS), online softmax + PV gather
        const float* rp = SC + row*SCS;
        #pragma unroll 4
        for (int j4 = 0; j4 < 32; j4++) {
            float4 x4 = *(const float4*)(rp + j4*4);
            float xs[4] = {x4.x, x4.y, x4.z, x4.w};
            #pragma unroll
            for (int u = 0; u < 4; u++) {
                float x = xs[u];
                int t = t0 + j4*4 + u;
                if (x > m) {
                    float r = __expf(m - x);
                    den = den * r + 1.f;
                    const float4* vr = (const float4*)(vbase + (size_t)t * D_);
                    #pragma unroll
                    for (int jj = 0; jj < 8; jj++) {
                        float4 v = vr[jj];
                        o4[jj].x = fmaf(o4[jj].x, r, v.x);
                        o4[jj].y = fmaf(o4[jj].y, r, v.y);
                        o4[jj].z = fmaf(o4[jj].z, r, v.z);
                        o4[jj].w = fmaf(o4[jj].w, r, v.w);
                    }
                    m = x;
                } else {
                    float dx = x - m;
                    if (dx > -95.0f) {      // exp underflows to exact 0 below this
                        float w = __expf(dx);
                        den += w;
                        const float4* vr = (const float4*)(vbase + (size_t)t * D_);
                        #pragma unroll
                        for (int jj = 0; jj < 8; jj++) {
                            float4 v = vr[jj];
                            o4[jj].x = fmaf(w, v.x, o4[jj].x);
                            o4[jj].y = fmaf(w, v.y, o4[jj].y);
                            o4[jj].z = fmaf(w, v.z, o4[jj].z);
                            o4[jj].w = fmaf(w, v.w, o4[jj].w);
                        }
                    }
                }
            }
        }
        __syncthreads();   // scan done before next spill / B restage
    }

    // ---- write out: o/den -> concat[b, s0+row, h*64 + half*32 ..] ----
    float inv = 1.f / den;
    float* op = g_concat + ((size_t)(b*2048 + s0 + row))*D_ + h*64 + half*32;
    #pragma unroll
    for (int jj = 0; jj < 8; jj++) {
        float4 r = o4[jj];
        r.x *= inv; r.y *= inv; r.z *= inv; r.w *= inv;
        *(float4*)(op + jj*4) = r;
    }
}

// ---------------- launcher ----------------
extern "C" void kernel_launch(void* const* d_in, const int* in_sizes, int n_in,
                              void* d_out, int out_size) {
    const float* q    = (const float*)d_in[0];
    // d_in[1] = k (unused in reference forward)
    const float* v    = (const float*)d_in[2];
    const float* Wv   = (const float*)d_in[3];
    const float* bv   = (const float*)d_in[4];
    const float* W_A  = (const float*)d_in[5];
    const float* W_A2 = (const float*)d_in[6];
    const float* Wo   = (const float*)d_in[7];
    const float* bo   = (const float*)d_in[8];
    float* out = (float*)d_out;

    float* vp;     cudaGetSymbolAddress((void**)&vp,     g_vp);
    float* concat; cudaGetSymbolAddress((void**)&concat, g_concat);

    cudaFuncSetAttribute(fused_attn_kernel,
                         cudaFuncAttributeMaxDynamicSharedMemorySize, SMEM_FUSED);

    compute_L_kernel<<<H_, 256>>>(W_A, W_A2);
    xy_kernel<<<B_*S_, 512>>>(q, W_A2);
    sgemm_nn_bias<<<dim3(D_/128, (B_*S_)/128), 256>>>(B_*S_, D_, D_, v, Wv, bv, vp);
    fused_attn_kernel<<<dim3(S_/128, BH_), 256, SMEM_FUSED>>>();
    sgemm_nn_bias<<<dim3(D_/128, (B_*S_)/128), 256>>>(B_*S_, D_, D_, concat, Wo, bo, out);
}